// round 5
// baseline (speedup 1.0000x reference)
#include <cuda_runtime.h>
#include <cstdint>

// Problem constants
#define NB   32
#define CH   64
#define HH   112
#define WW   112
#define HWSZ (HH*WW)             // 12544
#define PIX  (NB*HWSZ)           // 401408
#define ELEMS (NB*CH*HWSZ)       // 25690112
#define NW   576                 // 64 oc * 9 taps
#define EPSV 1e-5

// Scratch (device globals only)
__device__ unsigned long long g_xbits[PIX];          // packed activation signs
__device__ unsigned long long g_wpad[CH*10];         // packed weight signs, padded 10/channel
__device__ short              g_D[16*CH];            // border deficit per pattern x channel
__device__ float              g_scale[CH];           // mean |w| per output channel
__device__ long long          g_S1[CH];              // exact sum of s
__device__ long long          g_S2[CH];              // exact sum of s^2
__device__ short              g_sint[ELEMS];         // conv integer results (NCHW)

// ---------------------------------------------------------------------------
// K0: weight prep. 1 block, 576 threads. Packs signs (padded 10/channel),
// per-channel mean|w|, zeroes stat accumulators, builds the 16-pattern
// border-deficit table:  D[pat][o] = sum_{t invalid} (64 - 2*popc(w_ot))
// so that  s = 576 - 2*acc_all - D  (acc_all computed with zero-filled taps).
// ---------------------------------------------------------------------------
__global__ void k0_prep(const float* __restrict__ wflat) {
    __shared__ float         abss[NW];
    __shared__ unsigned char wps[NW];
    int t = threadIdx.x;           // 0..575
    int o = t / 9, tap = t % 9;
    unsigned long long bits = 0ull;
    float asum = 0.0f;
    #pragma unroll 8
    for (int i = 0; i < CH; i++) {
        float w = wflat[(o * CH + i) * 9 + tap];
        bits |= (unsigned long long)(__float_as_uint(w) >> 31) << i;
        asum += fabsf(w);
    }
    g_wpad[o * 10 + tap] = bits;
    wps[t]  = (unsigned char)__popcll(bits);
    abss[t] = asum;
    __syncthreads();
    if (t < CH) {
        float s = 0.0f;
        #pragma unroll
        for (int j = 0; j < 9; j++) s += abss[t * 9 + j];
        g_scale[t] = s * (1.0f / (float)NW);
        g_S1[t] = 0ll;
        g_S2[t] = 0ll;
        g_wpad[t * 10 + 9] = 0ull;   // padding slot
    }
    // pattern bit0=top(h==0), 1=bottom(h==111), 2=left(w==0), 3=right(w==111)
    for (int idx = t; idx < 16 * CH; idx += NW) {
        int p = idx >> 6, o2 = idx & 63;
        unsigned m = 0;
        if (p & 1) m |= 0x007;   // taps 0,1,2
        if (p & 2) m |= 0x1C0;   // taps 6,7,8
        if (p & 4) m |= 0x049;   // taps 0,3,6
        if (p & 8) m |= 0x124;   // taps 2,5,8
        int d = 0;
        while (m) { int tt = __ffs(m) - 1; m &= m - 1; d += 64 - 2 * (int)wps[o2 * 9 + tt]; }
        g_D[idx] = (short)d;
    }
}

// ---------------------------------------------------------------------------
// K1: pack sign bits of x. 4 pixels per thread, float4 loads per channel.
// ---------------------------------------------------------------------------
__global__ void __launch_bounds__(256) k1_pack(const float* __restrict__ x) {
    int t  = blockIdx.x * 256 + threadIdx.x;       // PIX/4 threads exactly
    int pb = t * 4;
    int n  = pb / HWSZ;
    int hw = pb % HWSZ;                            // HWSZ%4==0 -> same n for all 4
    const float* xp = x + (size_t)n * CH * HWSZ + hw;
    unsigned long long b0 = 0, b1 = 0, b2 = 0, b3 = 0;
    #pragma unroll 8
    for (int c = 0; c < CH; c++) {
        float4 v = *(const float4*)(xp + (size_t)c * HWSZ);
        b0 |= (unsigned long long)(__float_as_uint(v.x) >> 31) << c;
        b1 |= (unsigned long long)(__float_as_uint(v.y) >> 31) << c;
        b2 |= (unsigned long long)(__float_as_uint(v.z) >> 31) << c;
        b3 |= (unsigned long long)(__float_as_uint(v.w) >> 31) << c;
    }
    ulonglong2* dst = (ulonglong2*)(g_xbits + pb);
    dst[0] = make_ulonglong2(b0, b1);
    dst[1] = make_ulonglong2(b2, b3);
}

// ---------------------------------------------------------------------------
// K2: binary conv via xor+popc. Each thread: 4 consecutive pixels (same row),
// all 64 output channels; weights loaded once per channel (amortized 4x).
// ---------------------------------------------------------------------------
__global__ void __launch_bounds__(256) k2_conv(void) {
    __shared__ __align__(16) unsigned long long ws[CH * 10];
    __shared__ short Dt[16 * CH];
    __shared__ int bs1[CH], bs2[CH];

    int tid = threadIdx.x;
    #pragma unroll
    for (int j = tid; j < CH * 10; j += 256) ws[j] = g_wpad[j];
    #pragma unroll
    for (int j = tid; j < 16 * CH; j += 256) Dt[j] = g_D[j];
    if (tid < CH) { bs1[tid] = 0; bs2[tid] = 0; }
    __syncthreads();

    int g  = blockIdx.x * 256 + tid;   // group id: PIX/4 = 392*256 exact
    int p0 = g * 4;
    int n  = p0 / HWSZ;
    int hw = p0 % HWSZ;
    int h  = hw / WW;
    int w0 = hw % WW;                  // multiple of 4; group never spans rows

    // 3x6 window of packed words (rows h-1..h+1, cols w0-1..w0+4)
    unsigned long long xb[3][6];
    const unsigned long long* xim = g_xbits + (size_t)n * HWSZ;
    #pragma unroll
    for (int r = 0; r < 3; r++) {
        int hh = h + r - 1;
        bool rv = (hh >= 0) & (hh < HH);
        const unsigned long long* row = xim + hh * WW;
        xb[r][0] = (rv && w0 > 0) ? row[w0 - 1] : 0ull;
        if (rv) {
            ulonglong2 a = *(const ulonglong2*)(row + w0);
            ulonglong2 b = *(const ulonglong2*)(row + w0 + 2);
            xb[r][1] = a.x; xb[r][2] = a.y; xb[r][3] = b.x; xb[r][4] = b.y;
        } else {
            xb[r][1] = xb[r][2] = xb[r][3] = xb[r][4] = 0ull;
        }
        xb[r][5] = (rv && (w0 + 4 < WW)) ? row[w0 + 4] : 0ull;
    }

    int tb   = (h == 0) | ((h == HH - 1) << 1);
    const short* D0 = Dt + ((tb | ((w0 == 0) << 2)) << 6);
    const short* Dm = Dt + (tb << 6);
    const short* D3 = Dt + ((tb | ((w0 + 3 == WW - 1) << 3)) << 6);

    size_t obase = (size_t)n * CH * HWSZ + hw;
    bool lane0 = ((tid & 31) == 0);

    for (int o = 0; o < CH; o++) {
        const ulonglong2* wv = (const ulonglong2*)(ws + o * 10);
        ulonglong2 w01 = wv[0], w23 = wv[1], w45 = wv[2], w67 = wv[3];
        unsigned long long wt[9] = { w01.x, w01.y, w23.x, w23.y,
                                     w45.x, w45.y, w67.x, w67.y, ws[o * 10 + 8] };
        int s[4];
        #pragma unroll
        for (int j = 0; j < 4; j++) {
            int acc = 0;
            #pragma unroll
            for (int r = 0; r < 3; r++)
                #pragma unroll
                for (int c = 0; c < 3; c++)
                    acc += __popcll(xb[r][j + c] ^ wt[r * 3 + c]);
            s[j] = 576 - 2 * acc;
        }
        s[0] -= (int)D0[o];
        s[1] -= (int)Dm[o];
        s[2] -= (int)Dm[o];
        s[3] -= (int)D3[o];

        *(short4*)(g_sint + obase + (size_t)o * HWSZ) =
            make_short4((short)s[0], (short)s[1], (short)s[2], (short)s[3]);

        int t1 = s[0] + s[1] + s[2] + s[3];
        int t2 = s[0]*s[0] + s[1]*s[1] + s[2]*s[2] + s[3]*s[3];
        t1 = __reduce_add_sync(0xffffffffu, t1);
        t2 = __reduce_add_sync(0xffffffffu, t2);
        if (lane0) { atomicAdd(&bs1[o], t1); atomicAdd(&bs2[o], t2); }
    }
    __syncthreads();
    if (tid < CH) {
        atomicAdd((unsigned long long*)&g_S1[tid], (unsigned long long)(long long)bs1[tid]);
        atomicAdd((unsigned long long*)&g_S2[tid], (unsigned long long)(long long)bs2[tid]);
    }
}

// ---------------------------------------------------------------------------
// K4: BN fold (per-block preamble, exact double) + elementwise epilogue
//     out = s*A[o] + B[o] + x,  16 float4 per thread, streaming hints.
// ---------------------------------------------------------------------------
__global__ void __launch_bounds__(256) k4_epilogue(
    const float* __restrict__ x, const float* __restrict__ gamma,
    const float* __restrict__ beta, float* __restrict__ out)
{
    __shared__ float sA[CH], sB[CH];
    int tid = threadIdx.x;
    if (tid < CH) {
        const double cnt = (double)PIX;
        double sc   = (double)g_scale[tid];
        double mean = sc * ((double)g_S1[tid] / cnt);
        double ex2  = sc * sc * ((double)g_S2[tid] / cnt);
        double var  = ex2 - mean * mean;
        double inv  = (double)gamma[tid] * rsqrt(var + EPSV);
        sA[tid] = (float)(sc * inv);
        sB[tid] = (float)((double)beta[tid] - mean * inv);
    }
    __syncthreads();

    int base = blockIdx.x * 4096;                  // ELEMS/4 = 6422528 = 1568*4096
    #pragma unroll 4
    for (int it = 0; it < 16; it++) {
        int i = base + it * 256 + tid;
        int o = (i / (HWSZ / 4)) & (CH - 1);
        float a = sA[o], b = sB[o];
        float4 xv = __ldcs((const float4*)x + i);
        short4 sv = __ldcs((const short4*)g_sint + i);
        float4 r;
        r.x = fmaf((float)sv.x, a, b) + xv.x;
        r.y = fmaf((float)sv.y, a, b) + xv.y;
        r.z = fmaf((float)sv.z, a, b) + xv.z;
        r.w = fmaf((float)sv.w, a, b) + xv.w;
        __stcs((float4*)out + i, r);
    }
}

// ---------------------------------------------------------------------------
extern "C" void kernel_launch(void* const* d_in, const int* in_sizes, int n_in,
                              void* d_out, int out_size) {
    const float* x     = (const float*)d_in[0];
    const float* wts   = (const float*)d_in[1];
    const float* gamma = (const float*)d_in[2];
    const float* beta  = (const float*)d_in[3];
    float* out = (float*)d_out;

    k0_prep<<<1, NW>>>(wts);
    k1_pack<<<PIX / 4 / 256, 256>>>(x);
    k2_conv<<<PIX / 4 / 256, 256>>>();
    k4_epilogue<<<1568, 256>>>(x, gamma, beta, out);
}